// round 5
// baseline (speedup 1.0000x reference)
#include <cuda_runtime.h>
#include <cuda_fp16.h>
#include <cstdint>

#define NMAX 100000
#define EMAX 1600000
#define ETOT (EMAX + NMAX)
#define SCAN_CHUNK 1024
#define NBMAX ((NMAX + SCAN_CHUNK - 1) / SCAN_CHUNK)
#define HIST_BLOCKS 1184   // 8 * 148 SMs, grid-stride over edges

// ---------------------------------------------------------------------------
// Static scratch (zero-initialized at module load; kernels restore the
// zero-invariants they rely on so CUDA-graph replays stay deterministic).
// ---------------------------------------------------------------------------
__device__ __half g_h1h[NMAX * 64];  // x @ W1   (fp16 storage, fp32 math)
__device__ float  g_o1[NMAX * 64];   // relu(aggregate layer1) = input to GEMM2
__device__ float  g_h2[NMAX * 32];   // o1 @ W2  (fp32: adjacent to output)
__device__ float  g_as1[NMAX], g_ad1[NMAX];
__device__ float  g_as2[NMAX], g_ad2[NMAX];
__device__ int    g_deg[NMAX];       // invariant: zero at kernel_launch entry
__device__ int    g_off[NMAX + 1];
__device__ int    g_cur[NMAX];
__device__ int    g_csr[ETOT];       // src ids grouped by dst
// Decoupled-lookback state: hi32 = flag (0 none, 1 aggregate, 2 inclusive),
// lo32 = value. Invariant: zero at kernel_launch entry (reset by scatter).
__device__ unsigned long long g_scan[NBMAX];

// ---------------------------------------------------------------------------
// Single-pass exclusive scan of (deg[i] + 1) with decoupled lookback.
// Also zeroes g_deg for the next replay and writes off[n] = grand total.
// nb = ceil(n/1024) = 98 blocks, all co-resident on 148 SMs -> spin is safe.
// ---------------------------------------------------------------------------
__global__ void __launch_bounds__(256) scan_onepass_kernel(int n, int nb) {
    __shared__ int sm[256];
    __shared__ int s_excl;
    const int b = blockIdx.x;
    const int t = threadIdx.x;
    const int i0 = b * SCAN_CHUNK + t * 4;

    int v[4];
    int s = 0;
#pragma unroll
    for (int u = 0; u < 4; ++u) {
        int i = i0 + u;
        if (i < n) {
            v[u] = g_deg[i] + 1;   // +1 self-loop folded in
            g_deg[i] = 0;          // restore invariant for next replay
        } else v[u] = 0;
        s += v[u];
    }
    sm[t] = s;
    __syncthreads();
    for (int st = 1; st < 256; st <<= 1) {
        int a = (t >= st) ? sm[t - st] : 0;
        __syncthreads();
        sm[t] += a;
        __syncthreads();
    }
    const int incl = sm[t];        // inclusive over thread partials
    const int total = sm[255];

    if (t == 0) {
        unsigned long long pub = ((b == 0) ? (2ULL << 32) : (1ULL << 32)) |
                                 (unsigned int)total;
        atomicExch(&g_scan[b], pub);
        int excl = 0;
        if (b > 0) {
            int j = b - 1;
            for (;;) {
                unsigned long long st2;
                do {
                    st2 = atomicAdd(&g_scan[j], 0ULL);
                    if (!(st2 >> 32)) __nanosleep(40);
                } while (!(st2 >> 32));
                excl += (int)(unsigned int)st2;
                if ((st2 >> 32) == 2ULL) break;
                --j;
            }
            atomicExch(&g_scan[b], (2ULL << 32) | (unsigned int)(excl + total));
        }
        s_excl = excl;
    }
    __syncthreads();

    int pref = s_excl + (incl - s);   // exclusive prefix for first element
#pragma unroll
    for (int u = 0; u < 4; ++u) {
        int i = i0 + u;
        if (i < n) { g_off[i] = pref; g_cur[i] = pref; }
        pref += v[u];
    }
    if (b == nb - 1 && t == 255) g_off[n] = s_excl + total;
}

// ---------------------------------------------------------------------------
// Scatter src ids into CSR slots; also resets scan state for next replay.
// ---------------------------------------------------------------------------
__global__ void scatter_kernel(const int* __restrict__ ei, int e, int n, int nb) {
    int t = blockIdx.x * blockDim.x + threadIdx.x;
    if (t < nb) g_scan[t] = 0ULL;    // restore invariant
    if (t < e) {
        int src = ei[t];
        int dst = ei[e + t];
        int pos = atomicAdd(&g_cur[dst], 1);
        g_csr[pos] = src;
    } else if (t < e + n) {
        int i = t - e;
        int pos = atomicAdd(&g_cur[i], 1);
        g_csr[pos] = i;              // self-loop
    }
}

// ---------------------------------------------------------------------------
// GEMM body with fused alpha epilogue.
// H[n, M] = X[n, K] @ W[K, M]; as[i] = H[i]·a_s ; ad[i] = H[i]·a_d.
// Block = 64 nodes x M cols, 256 threads, register tile 4 x (M/16).
// TH = __half (layer 1 storage) or float (layer 2).
// ---------------------------------------------------------------------------
template <int K, int M, typename TH>
__device__ __forceinline__ void gemm_alpha_body(
    const float* __restrict__ X, const float* __restrict__ W,
    TH* __restrict__ H,
    const float* __restrict__ a_s, const float* __restrict__ a_d,
    float* __restrict__ as_out, float* __restrict__ ad_out,
    int n, int bid)
{
    constexpr int KC = 64;
    constexpr int XS = KC + 4;
    constexpr int TM = M / 16;        // 4 (M=64) or 2 (M=32)
    __shared__ float xs[64 * XS];
    __shared__ float ws[KC * M];

    const int tid = threadIdx.x;
    const int tx = tid & 15;
    const int ty = tid >> 4;
    const int nb = bid * 64;

    float acc[4][TM];
#pragma unroll
    for (int u = 0; u < 4; ++u)
#pragma unroll
        for (int v2 = 0; v2 < TM; ++v2) acc[u][v2] = 0.f;

    for (int kc = 0; kc < K; kc += KC) {
#pragma unroll
        for (int it = 0; it < (64 * KC / 4) / 256; ++it) {
            int idx = tid + it * 256;
            int r = idx / (KC / 4);
            int c4 = idx % (KC / 4);
            float4 v;
            int node = nb + r;
            if (node < n)
                v = *reinterpret_cast<const float4*>(X + (size_t)node * K + kc + c4 * 4);
            else
                v = make_float4(0.f, 0.f, 0.f, 0.f);
            *reinterpret_cast<float4*>(&xs[r * XS + c4 * 4]) = v;
        }
#pragma unroll
        for (int it = 0; it < (KC * M / 4) / 256; ++it) {
            int idx = tid + it * 256;
            int r = idx / (M / 4);
            int c4 = idx % (M / 4);
            *reinterpret_cast<float4*>(&ws[r * M + c4 * 4]) =
                *reinterpret_cast<const float4*>(W + (size_t)(kc + r) * M + c4 * 4);
        }
        __syncthreads();
#pragma unroll 8
        for (int k = 0; k < KC; ++k) {
            float xv[4];
#pragma unroll
            for (int u = 0; u < 4; ++u) xv[u] = xs[(ty * 4 + u) * XS + k];
            float wv[TM];
#pragma unroll
            for (int v2 = 0; v2 < TM; ++v2) wv[v2] = ws[k * M + tx * TM + v2];
#pragma unroll
            for (int u = 0; u < 4; ++u)
#pragma unroll
                for (int v2 = 0; v2 < TM; ++v2)
                    acc[u][v2] = fmaf(xv[u], wv[v2], acc[u][v2]);
        }
        __syncthreads();
    }

    float asv[TM], adv[TM];
#pragma unroll
    for (int v2 = 0; v2 < TM; ++v2) {
        asv[v2] = a_s[tx * TM + v2];
        adv[v2] = a_d[tx * TM + v2];
    }
#pragma unroll
    for (int u = 0; u < 4; ++u) {
        int node = nb + ty * 4 + u;
        float s = 0.f, d = 0.f;
#pragma unroll
        for (int v2 = 0; v2 < TM; ++v2) {
            float val = acc[u][v2];
            s = fmaf(val, asv[v2], s);
            d = fmaf(val, adv[v2], d);
        }
#pragma unroll
        for (int o = 8; o; o >>= 1) {
            s += __shfl_xor_sync(0xffffffffu, s, o);
            d += __shfl_xor_sync(0xffffffffu, d, o);
        }
        if (node < n) {
            if constexpr (sizeof(TH) == 2) {
                // fp16 store: TM=4 channels -> two half2 (8B contiguous)
                __half2* hp = reinterpret_cast<__half2*>(
                    (__half*)H + (size_t)node * M + tx * TM);
                hp[0] = __floats2half2_rn(acc[u][0], acc[u][1]);
                hp[1] = __floats2half2_rn(acc[u][2], acc[u][3]);
            } else {
#pragma unroll
                for (int v2 = 0; v2 < TM; ++v2)
                    ((float*)H)[(size_t)node * M + tx * TM + v2] = acc[u][v2];
            }
            if (tx == 0) { as_out[node] = s; ad_out[node] = d; }
        }
    }
}

// Fused: GEMM1 (+alpha1) blocks, then histogram blocks (independent work).
__global__ void __launch_bounds__(256) fused_gemm1_hist_kernel(
    const float* __restrict__ X, const float* __restrict__ W1,
    const float* __restrict__ aS1, const float* __restrict__ aD1,
    const int* __restrict__ ei, int n, int e, int gemm_blocks)
{
    if ((int)blockIdx.x < gemm_blocks) {
        gemm_alpha_body<128, 64, __half>(X, W1, g_h1h, aS1, aD1,
                                         g_as1, g_ad1, n, blockIdx.x);
    } else {
        int hb = gridDim.x - gemm_blocks;
        for (int t = (blockIdx.x - gemm_blocks) * 256 + threadIdx.x; t < e;
             t += hb * 256) {
            int dst = ei[e + t];
            atomicAdd(&g_deg[dst], 1);
        }
    }
}

__global__ void __launch_bounds__(256) gemm2_kernel(
    const float* __restrict__ W2,
    const float* __restrict__ aS2, const float* __restrict__ aD2, int n)
{
    gemm_alpha_body<64, 32, float>(g_o1, W2, g_h2, aS2, aD2,
                                   g_as2, g_ad2, n, blockIdx.x);
}

// ---------------------------------------------------------------------------
// Gather layer 1: warp per destination node. D=64, lane owns 2 channels
// (one half2 = 4B -> 128B per edge). fp32 accumulation.
// out = relu( (sum_e w_e * h[src_e]) / (sum_e w_e + 1e-16) + b )
// ---------------------------------------------------------------------------
__global__ void __launch_bounds__(256) gather64_kernel(
    const float* __restrict__ b, int n)
{
    int node = (blockIdx.x * blockDim.x + threadIdx.x) >> 5;
    int lane = threadIdx.x & 31;
    if (node >= n) return;
    int p0 = g_off[node], p1 = g_off[node + 1];
    float advl = g_ad1[node];
    float sum = 0.f, a0 = 0.f, a1 = 0.f;
#pragma unroll 4
    for (int p = p0; p < p1; ++p) {
        int src = g_csr[p];
        float ev = g_as1[src] + advl;
        ev = ev > 0.f ? ev : 0.2f * ev;
        float w = __expf(ev);
        __half2 hv2 = *reinterpret_cast<const __half2*>(
            g_h1h + (size_t)src * 64 + lane * 2);
        float2 hv = __half22float2(hv2);
        sum += w;
        a0 = fmaf(w, hv.x, a0);
        a1 = fmaf(w, hv.y, a1);
    }
    float inv = 1.f / (sum + 1e-16f);
    float2 o;
    o.x = fmaxf(fmaf(a0, inv, b[lane * 2]), 0.f);
    o.y = fmaxf(fmaf(a1, inv, b[lane * 2 + 1]), 0.f);
    *reinterpret_cast<float2*>(g_o1 + (size_t)node * 64 + lane * 2) = o;
}

// ---------------------------------------------------------------------------
// Gather layer 2 + fused log_softmax: warp per destination, lane = channel.
// ---------------------------------------------------------------------------
__global__ void __launch_bounds__(256) gather32_kernel(
    const float* __restrict__ b, float* __restrict__ out, int n)
{
    int node = (blockIdx.x * blockDim.x + threadIdx.x) >> 5;
    int lane = threadIdx.x & 31;
    if (node >= n) return;
    int p0 = g_off[node], p1 = g_off[node + 1];
    float advl = g_ad2[node];
    float sum = 0.f, acc = 0.f;
#pragma unroll 4
    for (int p = p0; p < p1; ++p) {
        int src = g_csr[p];
        float ev = g_as2[src] + advl;
        ev = ev > 0.f ? ev : 0.2f * ev;
        float w = __expf(ev);
        float hv = g_h2[(size_t)src * 32 + lane];
        sum += w;
        acc = fmaf(w, hv, acc);
    }
    float v = fmaf(acc, 1.f / (sum + 1e-16f), b[lane]);
    float m = v;
#pragma unroll
    for (int o = 16; o; o >>= 1) m = fmaxf(m, __shfl_xor_sync(0xffffffffu, m, o));
    float ex = __expf(v - m);
    float s2 = ex;
#pragma unroll
    for (int o = 16; o; o >>= 1) s2 += __shfl_xor_sync(0xffffffffu, s2, o);
    out[(size_t)node * 32 + lane] = v - m - __logf(s2);
}

// ---------------------------------------------------------------------------
// Launch: 6 kernels, no runtime API calls.
// ---------------------------------------------------------------------------
extern "C" void kernel_launch(void* const* d_in, const int* in_sizes, int n_in,
                              void* d_out, int out_size) {
    const float* x   = (const float*)d_in[0];
    const int*   ei  = (const int*)d_in[1];     // int64 coerced to int32 by harness
    const float* W1  = (const float*)d_in[2];
    const float* aS1 = (const float*)d_in[3];
    const float* aD1 = (const float*)d_in[4];
    const float* b1  = (const float*)d_in[5];
    const float* W2  = (const float*)d_in[6];
    const float* aS2 = (const float*)d_in[7];
    const float* aD2 = (const float*)d_in[8];
    const float* b2  = (const float*)d_in[9];
    float* out = (float*)d_out;

    const int n = in_sizes[0] / 128;
    const int e = in_sizes[1] / 2;
    const int etot = e + n;
    const int nb = (n + SCAN_CHUNK - 1) / SCAN_CHUNK;
    const int gemm1_blocks = (n + 63) / 64;

    // [GEMM1+alpha1 | edge histogram]  (g_deg arrives zeroed: invariant)
    fused_gemm1_hist_kernel<<<gemm1_blocks + HIST_BLOCKS, 256>>>(
        x, W1, aS1, aD1, ei, n, e, gemm1_blocks);

    // CSR offsets (single pass) + scatter
    scan_onepass_kernel<<<nb, 256>>>(n, nb);
    scatter_kernel<<<(etot + 255) / 256, 256>>>(ei, e, n, nb);

    // Layer 1 aggregate (+bias+ReLU)
    gather64_kernel<<<(n * 32 + 255) / 256, 256>>>(b1, n);

    // Layer 2
    gemm2_kernel<<<(n + 63) / 64, 256>>>(W2, aS2, aD2, n);
    gather32_kernel<<<(n * 32 + 255) / 256, 256>>>(b2, out, n);
}

// round 6
// speedup vs baseline: 1.0406x; 1.0406x over previous
#include <cuda_runtime.h>
#include <cuda_fp16.h>
#include <cstdint>

#define NMAX 100000
#define EMAX 1600000
#define ETOT (EMAX + NMAX)
#define SCAN_CHUNK 1024
#define NBMAX ((NMAX + SCAN_CHUNK - 1) / SCAN_CHUNK)
#define HIST_BLOCKS 1184   // 8 * 148 SMs, grid-stride over edges

// ---------------------------------------------------------------------------
// Static scratch (zero-initialized at module load; kernels restore the
// zero-invariants they rely on so CUDA-graph replays stay deterministic).
// ---------------------------------------------------------------------------
__device__ __half g_h1h[NMAX * 64];  // x @ W1   (fp16 storage, fp32 math)
__device__ float  g_o1[NMAX * 64];   // relu(aggregate layer1) = input to GEMM2
__device__ float  g_h2[NMAX * 32];   // o1 @ W2  (fp32: adjacent to output)
__device__ float  g_as1[NMAX], g_ad1[NMAX];
__device__ float  g_as2[NMAX], g_ad2[NMAX];
__device__ int    g_deg[NMAX];       // invariant: zero at kernel_launch entry
__device__ int    g_off[NMAX + 1];
__device__ int    g_cur[NMAX];
__device__ int    g_csr[ETOT];       // src ids grouped by dst
// Decoupled-lookback state: hi32 = flag (0 none, 1 aggregate, 2 inclusive),
// lo32 = value. Invariant: zero at kernel_launch entry (reset by scatter).
__device__ unsigned long long g_scan[NBMAX];

// ---------------------------------------------------------------------------
// Single-pass exclusive scan of (deg[i] + 1) with decoupled lookback.
// Also zeroes g_deg for the next replay and writes off[n] = grand total.
// ---------------------------------------------------------------------------
__global__ void __launch_bounds__(256) scan_onepass_kernel(int n, int nb) {
    __shared__ int sm[256];
    __shared__ int s_excl;
    const int b = blockIdx.x;
    const int t = threadIdx.x;
    const int i0 = b * SCAN_CHUNK + t * 4;

    int v[4];
    int s = 0;
#pragma unroll
    for (int u = 0; u < 4; ++u) {
        int i = i0 + u;
        if (i < n) {
            v[u] = g_deg[i] + 1;   // +1 self-loop folded in
            g_deg[i] = 0;          // restore invariant for next replay
        } else v[u] = 0;
        s += v[u];
    }
    sm[t] = s;
    __syncthreads();
    for (int st = 1; st < 256; st <<= 1) {
        int a = (t >= st) ? sm[t - st] : 0;
        __syncthreads();
        sm[t] += a;
        __syncthreads();
    }
    const int incl = sm[t];
    const int total = sm[255];

    if (t == 0) {
        unsigned long long pub = ((b == 0) ? (2ULL << 32) : (1ULL << 32)) |
                                 (unsigned int)total;
        atomicExch(&g_scan[b], pub);
        int excl = 0;
        if (b > 0) {
            int j = b - 1;
            for (;;) {
                unsigned long long st2;
                do {
                    st2 = atomicAdd(&g_scan[j], 0ULL);
                    if (!(st2 >> 32)) __nanosleep(40);
                } while (!(st2 >> 32));
                excl += (int)(unsigned int)st2;
                if ((st2 >> 32) == 2ULL) break;
                --j;
            }
            atomicExch(&g_scan[b], (2ULL << 32) | (unsigned int)(excl + total));
        }
        s_excl = excl;
    }
    __syncthreads();

    int pref = s_excl + (incl - s);
#pragma unroll
    for (int u = 0; u < 4; ++u) {
        int i = i0 + u;
        if (i < n) { g_off[i] = pref; g_cur[i] = pref; }
        pref += v[u];
    }
    if (b == nb - 1 && t == 255) g_off[n] = s_excl + total;
}

// ---------------------------------------------------------------------------
// Scatter src ids into CSR slots; also resets scan state for next replay.
// ---------------------------------------------------------------------------
__global__ void scatter_kernel(const int* __restrict__ ei, int e, int n, int nb) {
    int t = blockIdx.x * blockDim.x + threadIdx.x;
    if (t < nb) g_scan[t] = 0ULL;    // restore invariant
    if (t < e) {
        int src = ei[t];
        int dst = ei[e + t];
        int pos = atomicAdd(&g_cur[dst], 1);
        g_csr[pos] = src;
    } else if (t < e + n) {
        int i = t - e;
        int pos = atomicAdd(&g_cur[i], 1);
        g_csr[pos] = i;              // self-loop
    }
}

// ---------------------------------------------------------------------------
// GEMM body with fused alpha epilogue (unchanged from R5).
// ---------------------------------------------------------------------------
template <int K, int M, typename TH>
__device__ __forceinline__ void gemm_alpha_body(
    const float* __restrict__ X, const float* __restrict__ W,
    TH* __restrict__ H,
    const float* __restrict__ a_s, const float* __restrict__ a_d,
    float* __restrict__ as_out, float* __restrict__ ad_out,
    int n, int bid)
{
    constexpr int KC = 64;
    constexpr int XS = KC + 4;
    constexpr int TM = M / 16;
    __shared__ float xs[64 * XS];
    __shared__ float ws[KC * M];

    const int tid = threadIdx.x;
    const int tx = tid & 15;
    const int ty = tid >> 4;
    const int nb = bid * 64;

    float acc[4][TM];
#pragma unroll
    for (int u = 0; u < 4; ++u)
#pragma unroll
        for (int v2 = 0; v2 < TM; ++v2) acc[u][v2] = 0.f;

    for (int kc = 0; kc < K; kc += KC) {
#pragma unroll
        for (int it = 0; it < (64 * KC / 4) / 256; ++it) {
            int idx = tid + it * 256;
            int r = idx / (KC / 4);
            int c4 = idx % (KC / 4);
            float4 v;
            int node = nb + r;
            if (node < n)
                v = *reinterpret_cast<const float4*>(X + (size_t)node * K + kc + c4 * 4);
            else
                v = make_float4(0.f, 0.f, 0.f, 0.f);
            *reinterpret_cast<float4*>(&xs[r * XS + c4 * 4]) = v;
        }
#pragma unroll
        for (int it = 0; it < (KC * M / 4) / 256; ++it) {
            int idx = tid + it * 256;
            int r = idx / (M / 4);
            int c4 = idx % (M / 4);
            *reinterpret_cast<float4*>(&ws[r * M + c4 * 4]) =
                *reinterpret_cast<const float4*>(W + (size_t)(kc + r) * M + c4 * 4);
        }
        __syncthreads();
#pragma unroll 8
        for (int k = 0; k < KC; ++k) {
            float xv[4];
#pragma unroll
            for (int u = 0; u < 4; ++u) xv[u] = xs[(ty * 4 + u) * XS + k];
            float wv[TM];
#pragma unroll
            for (int v2 = 0; v2 < TM; ++v2) wv[v2] = ws[k * M + tx * TM + v2];
#pragma unroll
            for (int u = 0; u < 4; ++u)
#pragma unroll
                for (int v2 = 0; v2 < TM; ++v2)
                    acc[u][v2] = fmaf(xv[u], wv[v2], acc[u][v2]);
        }
        __syncthreads();
    }

    float asv[TM], adv[TM];
#pragma unroll
    for (int v2 = 0; v2 < TM; ++v2) {
        asv[v2] = a_s[tx * TM + v2];
        adv[v2] = a_d[tx * TM + v2];
    }
#pragma unroll
    for (int u = 0; u < 4; ++u) {
        int node = nb + ty * 4 + u;
        float s = 0.f, d = 0.f;
#pragma unroll
        for (int v2 = 0; v2 < TM; ++v2) {
            float val = acc[u][v2];
            s = fmaf(val, asv[v2], s);
            d = fmaf(val, adv[v2], d);
        }
#pragma unroll
        for (int o = 8; o; o >>= 1) {
            s += __shfl_xor_sync(0xffffffffu, s, o);
            d += __shfl_xor_sync(0xffffffffu, d, o);
        }
        if (node < n) {
            if constexpr (sizeof(TH) == 2) {
                __half2* hp = reinterpret_cast<__half2*>(
                    (__half*)H + (size_t)node * M + tx * TM);
                hp[0] = __floats2half2_rn(acc[u][0], acc[u][1]);
                hp[1] = __floats2half2_rn(acc[u][2], acc[u][3]);
            } else {
#pragma unroll
                for (int v2 = 0; v2 < TM; ++v2)
                    ((float*)H)[(size_t)node * M + tx * TM + v2] = acc[u][v2];
            }
            if (tx == 0) { as_out[node] = s; ad_out[node] = d; }
        }
    }
}

// Fused: GEMM1 (+alpha1) blocks, then histogram blocks (independent work).
__global__ void __launch_bounds__(256) fused_gemm1_hist_kernel(
    const float* __restrict__ X, const float* __restrict__ W1,
    const float* __restrict__ aS1, const float* __restrict__ aD1,
    const int* __restrict__ ei, int n, int e, int gemm_blocks)
{
    if ((int)blockIdx.x < gemm_blocks) {
        gemm_alpha_body<128, 64, __half>(X, W1, g_h1h, aS1, aD1,
                                         g_as1, g_ad1, n, blockIdx.x);
    } else {
        int hb = gridDim.x - gemm_blocks;
        for (int t = (blockIdx.x - gemm_blocks) * 256 + threadIdx.x; t < e;
             t += hb * 256) {
            int dst = ei[e + t];
            atomicAdd(&g_deg[dst], 1);
        }
    }
}

__global__ void __launch_bounds__(256) gemm2_kernel(
    const float* __restrict__ W2,
    const float* __restrict__ aS2, const float* __restrict__ aD2, int n)
{
    gemm_alpha_body<64, 32, float>(g_o1, W2, g_h2, aS2, aD2,
                                   g_as2, g_ad2, n, blockIdx.x);
}

// ---------------------------------------------------------------------------
// Gather layer 1 (issue-optimized): warp per destination node.
// Phase A: each LANE computes the softmax weight of a DIFFERENT edge
//          (kills the 32x-replicated scalar chain incl. __expf).
// Phase B: broadcast (w_j, src_j) by shfl; per-lane channel FMAs.
// out = relu( (sum w_e * h[src_e]) / (sum w_e + 1e-16) + b )
// ---------------------------------------------------------------------------
__global__ void __launch_bounds__(256) gather64_kernel(
    const float* __restrict__ b, int n)
{
    int node = (blockIdx.x * blockDim.x + threadIdx.x) >> 5;
    int lane = threadIdx.x & 31;
    if (node >= n) return;
    int p0 = g_off[node], p1 = g_off[node + 1];
    float advl = g_ad1[node];
    const __half2* hb = reinterpret_cast<const __half2*>(g_h1h) + lane;
    float sum = 0.f, a0 = 0.f, a1 = 0.f;

    for (int base = p0; base < p1; base += 32) {
        int p = base + lane;
        int src = 0;
        float w = 0.f;
        if (p < p1) {
            src = g_csr[p];
            float ev = g_as1[src] + advl;
            ev = ev > 0.f ? ev : 0.2f * ev;
            w = __expf(ev);
        }
        sum += w;
        int off = src * 32;               // half2 units per row
        int nc = min(32, p1 - base);
#pragma unroll 4
        for (int j = 0; j < nc; ++j) {
            float wj = __shfl_sync(0xffffffffu, w, j);
            int oj = __shfl_sync(0xffffffffu, off, j);
            float2 hv = __half22float2(hb[oj]);
            a0 = fmaf(wj, hv.x, a0);
            a1 = fmaf(wj, hv.y, a1);
        }
    }
#pragma unroll
    for (int o = 16; o; o >>= 1) sum += __shfl_xor_sync(0xffffffffu, sum, o);
    float inv = 1.f / (sum + 1e-16f);
    float2 o;
    o.x = fmaxf(fmaf(a0, inv, b[lane * 2]), 0.f);
    o.y = fmaxf(fmaf(a1, inv, b[lane * 2 + 1]), 0.f);
    *reinterpret_cast<float2*>(g_o1 + (size_t)node * 64 + lane * 2) = o;
}

// ---------------------------------------------------------------------------
// Gather layer 2 + fused log_softmax (same lane-parallel weight scheme).
// ---------------------------------------------------------------------------
__global__ void __launch_bounds__(256) gather32_kernel(
    const float* __restrict__ b, float* __restrict__ out, int n)
{
    int node = (blockIdx.x * blockDim.x + threadIdx.x) >> 5;
    int lane = threadIdx.x & 31;
    if (node >= n) return;
    int p0 = g_off[node], p1 = g_off[node + 1];
    float advl = g_ad2[node];
    const float* hb = g_h2 + lane;
    float sum = 0.f, acc = 0.f;

    for (int base = p0; base < p1; base += 32) {
        int p = base + lane;
        int src = 0;
        float w = 0.f;
        if (p < p1) {
            src = g_csr[p];
            float ev = g_as2[src] + advl;
            ev = ev > 0.f ? ev : 0.2f * ev;
            w = __expf(ev);
        }
        sum += w;
        int off = src * 32;
        int nc = min(32, p1 - base);
#pragma unroll 4
        for (int j = 0; j < nc; ++j) {
            float wj = __shfl_sync(0xffffffffu, w, j);
            int oj = __shfl_sync(0xffffffffu, off, j);
            acc = fmaf(wj, hb[oj], acc);
        }
    }
#pragma unroll
    for (int o = 16; o; o >>= 1) sum += __shfl_xor_sync(0xffffffffu, sum, o);

    float v = fmaf(acc, 1.f / (sum + 1e-16f), b[lane]);
    float m = v;
#pragma unroll
    for (int o = 16; o; o >>= 1) m = fmaxf(m, __shfl_xor_sync(0xffffffffu, m, o));
    float ex = __expf(v - m);
    float s2 = ex;
#pragma unroll
    for (int o = 16; o; o >>= 1) s2 += __shfl_xor_sync(0xffffffffu, s2, o);
    out[(size_t)node * 32 + lane] = v - m - __logf(s2);
}

// ---------------------------------------------------------------------------
// Launch: 6 kernels, no runtime API calls.
// ---------------------------------------------------------------------------
extern "C" void kernel_launch(void* const* d_in, const int* in_sizes, int n_in,
                              void* d_out, int out_size) {
    const float* x   = (const float*)d_in[0];
    const int*   ei  = (const int*)d_in[1];     // int64 coerced to int32 by harness
    const float* W1  = (const float*)d_in[2];
    const float* aS1 = (const float*)d_in[3];
    const float* aD1 = (const float*)d_in[4];
    const float* b1  = (const float*)d_in[5];
    const float* W2  = (const float*)d_in[6];
    const float* aS2 = (const float*)d_in[7];
    const float* aD2 = (const float*)d_in[8];
    const float* b2  = (const float*)d_in[9];
    float* out = (float*)d_out;

    const int n = in_sizes[0] / 128;
    const int e = in_sizes[1] / 2;
    const int etot = e + n;
    const int nb = (n + SCAN_CHUNK - 1) / SCAN_CHUNK;
    const int gemm1_blocks = (n + 63) / 64;

    // [GEMM1+alpha1 | edge histogram]  (g_deg arrives zeroed: invariant)
    fused_gemm1_hist_kernel<<<gemm1_blocks + HIST_BLOCKS, 256>>>(
        x, W1, aS1, aD1, ei, n, e, gemm1_blocks);

    // CSR offsets (single pass) + scatter
    scan_onepass_kernel<<<nb, 256>>>(n, nb);
    scatter_kernel<<<(etot + 255) / 256, 256>>>(ei, e, n, nb);

    // Layer 1 aggregate (+bias+ReLU)
    gather64_kernel<<<(n * 32 + 255) / 256, 256>>>(b1, n);

    // Layer 2
    gemm2_kernel<<<(n + 63) / 64, 256>>>(W2, aS2, aD2, n);
    gather32_kernel<<<(n * 32 + 255) / 256, 256>>>(b2, out, n);
}

// round 7
// speedup vs baseline: 1.0982x; 1.0553x over previous
#include <cuda_runtime.h>
#include <cuda_fp16.h>
#include <cstdint>

#define NMAX 100000
#define EMAX 1600000
#define ETOT (EMAX + NMAX)
#define SCAN_CHUNK 1024
#define NBMAX ((NMAX + SCAN_CHUNK - 1) / SCAN_CHUNK)
#define HIST_BLOCKS 1184   // 8 * 148 SMs, grid-stride over edges

// ---------------------------------------------------------------------------
// Static scratch (zero-initialized at module load; kernels restore the
// zero-invariants they rely on so CUDA-graph replays stay deterministic).
// ---------------------------------------------------------------------------
__device__ __half g_h1h[NMAX * 64];  // x @ W1   (fp16 storage, fp32 math)
__device__ float  g_o1[NMAX * 64];   // relu(aggregate layer1) = input to GEMM2
__device__ float  g_h2[NMAX * 32];   // o1 @ W2  (fp32: adjacent to output)
__device__ float  g_as1[NMAX], g_ad1[NMAX];
__device__ float  g_as2[NMAX], g_ad2[NMAX];
__device__ int    g_deg[NMAX];       // invariant: zero at kernel_launch entry
__device__ int    g_off[NMAX + 1];
__device__ int    g_cur[NMAX];
__device__ int    g_csr[ETOT];       // src ids grouped by dst
// Decoupled-lookback state: hi32 = flag (0 none, 1 aggregate, 2 inclusive),
// lo32 = value. Invariant: zero at kernel_launch entry (reset by scatter).
__device__ unsigned long long g_scan[NBMAX];

// ---------------------------------------------------------------------------
// Single-pass exclusive scan of (deg[i] + 1) with decoupled lookback.
// Also zeroes g_deg for the next replay and writes off[n] = grand total.
// ---------------------------------------------------------------------------
__global__ void __launch_bounds__(256) scan_onepass_kernel(int n, int nb) {
    __shared__ int sm[256];
    __shared__ int s_excl;
    const int b = blockIdx.x;
    const int t = threadIdx.x;
    const int i0 = b * SCAN_CHUNK + t * 4;

    int v[4];
    int s = 0;
#pragma unroll
    for (int u = 0; u < 4; ++u) {
        int i = i0 + u;
        if (i < n) {
            v[u] = g_deg[i] + 1;   // +1 self-loop folded in
            g_deg[i] = 0;          // restore invariant for next replay
        } else v[u] = 0;
        s += v[u];
    }
    sm[t] = s;
    __syncthreads();
    for (int st = 1; st < 256; st <<= 1) {
        int a = (t >= st) ? sm[t - st] : 0;
        __syncthreads();
        sm[t] += a;
        __syncthreads();
    }
    const int incl = sm[t];
    const int total = sm[255];

    if (t == 0) {
        unsigned long long pub = ((b == 0) ? (2ULL << 32) : (1ULL << 32)) |
                                 (unsigned int)total;
        atomicExch(&g_scan[b], pub);
        int excl = 0;
        if (b > 0) {
            int j = b - 1;
            for (;;) {
                unsigned long long st2;
                do {
                    st2 = atomicAdd(&g_scan[j], 0ULL);
                    if (!(st2 >> 32)) __nanosleep(40);
                } while (!(st2 >> 32));
                excl += (int)(unsigned int)st2;
                if ((st2 >> 32) == 2ULL) break;
                --j;
            }
            atomicExch(&g_scan[b], (2ULL << 32) | (unsigned int)(excl + total));
        }
        s_excl = excl;
    }
    __syncthreads();

    int pref = s_excl + (incl - s);
#pragma unroll
    for (int u = 0; u < 4; ++u) {
        int i = i0 + u;
        if (i < n) { g_off[i] = pref; g_cur[i] = pref; }
        pref += v[u];
    }
    if (b == nb - 1 && t == 255) g_off[n] = s_excl + total;
}

// ---------------------------------------------------------------------------
// Scatter src ids into CSR slots; also resets scan state for next replay.
// ---------------------------------------------------------------------------
__global__ void scatter_kernel(const int* __restrict__ ei, int e, int n, int nb) {
    int t = blockIdx.x * blockDim.x + threadIdx.x;
    if (t < nb) g_scan[t] = 0ULL;    // restore invariant
    if (t < e) {
        int src = ei[t];
        int dst = ei[e + t];
        int pos = atomicAdd(&g_cur[dst], 1);
        g_csr[pos] = src;
    } else if (t < e + n) {
        int i = t - e;
        int pos = atomicAdd(&g_cur[i], 1);
        g_csr[pos] = i;              // self-loop
    }
}

// ---------------------------------------------------------------------------
// GEMM body with fused alpha epilogue (unchanged from R6).
// ---------------------------------------------------------------------------
template <int K, int M, typename TH>
__device__ __forceinline__ void gemm_alpha_body(
    const float* __restrict__ X, const float* __restrict__ W,
    TH* __restrict__ H,
    const float* __restrict__ a_s, const float* __restrict__ a_d,
    float* __restrict__ as_out, float* __restrict__ ad_out,
    int n, int bid)
{
    constexpr int KC = 64;
    constexpr int XS = KC + 4;
    constexpr int TM = M / 16;
    __shared__ float xs[64 * XS];
    __shared__ float ws[KC * M];

    const int tid = threadIdx.x;
    const int tx = tid & 15;
    const int ty = tid >> 4;
    const int nb = bid * 64;

    float acc[4][TM];
#pragma unroll
    for (int u = 0; u < 4; ++u)
#pragma unroll
        for (int v2 = 0; v2 < TM; ++v2) acc[u][v2] = 0.f;

    for (int kc = 0; kc < K; kc += KC) {
#pragma unroll
        for (int it = 0; it < (64 * KC / 4) / 256; ++it) {
            int idx = tid + it * 256;
            int r = idx / (KC / 4);
            int c4 = idx % (KC / 4);
            float4 v;
            int node = nb + r;
            if (node < n)
                v = *reinterpret_cast<const float4*>(X + (size_t)node * K + kc + c4 * 4);
            else
                v = make_float4(0.f, 0.f, 0.f, 0.f);
            *reinterpret_cast<float4*>(&xs[r * XS + c4 * 4]) = v;
        }
#pragma unroll
        for (int it = 0; it < (KC * M / 4) / 256; ++it) {
            int idx = tid + it * 256;
            int r = idx / (M / 4);
            int c4 = idx % (M / 4);
            *reinterpret_cast<float4*>(&ws[r * M + c4 * 4]) =
                *reinterpret_cast<const float4*>(W + (size_t)(kc + r) * M + c4 * 4);
        }
        __syncthreads();
#pragma unroll 8
        for (int k = 0; k < KC; ++k) {
            float xv[4];
#pragma unroll
            for (int u = 0; u < 4; ++u) xv[u] = xs[(ty * 4 + u) * XS + k];
            float wv[TM];
#pragma unroll
            for (int v2 = 0; v2 < TM; ++v2) wv[v2] = ws[k * M + tx * TM + v2];
#pragma unroll
            for (int u = 0; u < 4; ++u)
#pragma unroll
                for (int v2 = 0; v2 < TM; ++v2)
                    acc[u][v2] = fmaf(xv[u], wv[v2], acc[u][v2]);
        }
        __syncthreads();
    }

    float asv[TM], adv[TM];
#pragma unroll
    for (int v2 = 0; v2 < TM; ++v2) {
        asv[v2] = a_s[tx * TM + v2];
        adv[v2] = a_d[tx * TM + v2];
    }
#pragma unroll
    for (int u = 0; u < 4; ++u) {
        int node = nb + ty * 4 + u;
        float s = 0.f, d = 0.f;
#pragma unroll
        for (int v2 = 0; v2 < TM; ++v2) {
            float val = acc[u][v2];
            s = fmaf(val, asv[v2], s);
            d = fmaf(val, adv[v2], d);
        }
#pragma unroll
        for (int o = 8; o; o >>= 1) {
            s += __shfl_xor_sync(0xffffffffu, s, o);
            d += __shfl_xor_sync(0xffffffffu, d, o);
        }
        if (node < n) {
            if constexpr (sizeof(TH) == 2) {
                __half2* hp = reinterpret_cast<__half2*>(
                    (__half*)H + (size_t)node * M + tx * TM);
                hp[0] = __floats2half2_rn(acc[u][0], acc[u][1]);
                hp[1] = __floats2half2_rn(acc[u][2], acc[u][3]);
            } else {
#pragma unroll
                for (int v2 = 0; v2 < TM; ++v2)
                    ((float*)H)[(size_t)node * M + tx * TM + v2] = acc[u][v2];
            }
            if (tx == 0) { as_out[node] = s; ad_out[node] = d; }
        }
    }
}

// Fused: GEMM1 (+alpha1) blocks, then histogram blocks (independent work).
__global__ void __launch_bounds__(256) fused_gemm1_hist_kernel(
    const float* __restrict__ X, const float* __restrict__ W1,
    const float* __restrict__ aS1, const float* __restrict__ aD1,
    const int* __restrict__ ei, int n, int e, int gemm_blocks)
{
    if ((int)blockIdx.x < gemm_blocks) {
        gemm_alpha_body<128, 64, __half>(X, W1, g_h1h, aS1, aD1,
                                         g_as1, g_ad1, n, blockIdx.x);
    } else {
        int hb = gridDim.x - gemm_blocks;
        for (int t = (blockIdx.x - gemm_blocks) * 256 + threadIdx.x; t < e;
             t += hb * 256) {
            int dst = ei[e + t];
            atomicAdd(&g_deg[dst], 1);
        }
    }
}

__global__ void __launch_bounds__(256) gemm2_kernel(
    const float* __restrict__ W2,
    const float* __restrict__ aS2, const float* __restrict__ aD2, int n)
{
    gemm_alpha_body<64, 32, float>(g_o1, W2, g_h2, aS2, aD2,
                                   g_as2, g_ad2, n, blockIdx.x);
}

// ---------------------------------------------------------------------------
// Gather layer 1: warp per destination node, smem-staged edge queue.
// Phase A: each LANE computes the softmax weight of a DIFFERENT edge and
//          stages (w, row-offset) as one float2 in the per-warp queue.
// Phase B: per edge, ONE broadcast LDS.64 replaces two SHFLs; per-lane
//          half2 load + 2 FFMA (fp32 accumulation).
// ---------------------------------------------------------------------------
__global__ void __launch_bounds__(256) gather64_kernel(
    const float* __restrict__ b, int n)
{
    __shared__ float2 stage[8][32];
    int node = (blockIdx.x * blockDim.x + threadIdx.x) >> 5;
    int lane = threadIdx.x & 31;
    int wid = (threadIdx.x >> 5) & 7;
    if (node >= n) return;
    int p0 = g_off[node], p1 = g_off[node + 1];
    float advl = g_ad1[node];
    const __half2* hb = reinterpret_cast<const __half2*>(g_h1h) + lane;
    float sum = 0.f, a0 = 0.f, a1 = 0.f;

    for (int base = p0; base < p1; base += 32) {
        int p = base + lane;
        int src = 0;
        float w = 0.f;
        if (p < p1) {
            src = g_csr[p];
            float ev = g_as1[src] + advl;
            ev = ev > 0.f ? ev : 0.2f * ev;
            w = __expf(ev);
        }
        sum += w;
        stage[wid][lane] = make_float2(w, __int_as_float(src * 32));
        __syncwarp();
        int nc = min(32, p1 - base);
#pragma unroll 4
        for (int j = 0; j < nc; ++j) {
            float2 sj = stage[wid][j];
            float2 hv = __half22float2(hb[__float_as_int(sj.y)]);
            a0 = fmaf(sj.x, hv.x, a0);
            a1 = fmaf(sj.x, hv.y, a1);
        }
        __syncwarp();    // queue reuse fence for next chunk
    }
#pragma unroll
    for (int o = 16; o; o >>= 1) sum += __shfl_xor_sync(0xffffffffu, sum, o);
    float inv = 1.f / (sum + 1e-16f);
    float2 o;
    o.x = fmaxf(fmaf(a0, inv, b[lane * 2]), 0.f);
    o.y = fmaxf(fmaf(a1, inv, b[lane * 2 + 1]), 0.f);
    *reinterpret_cast<float2*>(g_o1 + (size_t)node * 64 + lane * 2) = o;
}

// ---------------------------------------------------------------------------
// Gather layer 2 + fused log_softmax: same smem-staged scheme, fp32 h2.
// ---------------------------------------------------------------------------
__global__ void __launch_bounds__(256) gather32_kernel(
    const float* __restrict__ b, float* __restrict__ out, int n)
{
    __shared__ float2 stage[8][32];
    int node = (blockIdx.x * blockDim.x + threadIdx.x) >> 5;
    int lane = threadIdx.x & 31;
    int wid = (threadIdx.x >> 5) & 7;
    if (node >= n) return;
    int p0 = g_off[node], p1 = g_off[node + 1];
    float advl = g_ad2[node];
    const float* hb = g_h2 + lane;
    float sum = 0.f, acc = 0.f;

    for (int base = p0; base < p1; base += 32) {
        int p = base + lane;
        int src = 0;
        float w = 0.f;
        if (p < p1) {
            src = g_csr[p];
            float ev = g_as2[src] + advl;
            ev = ev > 0.f ? ev : 0.2f * ev;
            w = __expf(ev);
        }
        sum += w;
        stage[wid][lane] = make_float2(w, __int_as_float(src * 32));
        __syncwarp();
        int nc = min(32, p1 - base);
#pragma unroll 4
        for (int j = 0; j < nc; ++j) {
            float2 sj = stage[wid][j];
            acc = fmaf(sj.x, hb[__float_as_int(sj.y)], acc);
        }
        __syncwarp();
    }
#pragma unroll
    for (int o = 16; o; o >>= 1) sum += __shfl_xor_sync(0xffffffffu, sum, o);

    float v = fmaf(acc, 1.f / (sum + 1e-16f), b[lane]);
    float m = v;
#pragma unroll
    for (int o = 16; o; o >>= 1) m = fmaxf(m, __shfl_xor_sync(0xffffffffu, m, o));
    float ex = __expf(v - m);
    float s2 = ex;
#pragma unroll
    for (int o = 16; o; o >>= 1) s2 += __shfl_xor_sync(0xffffffffu, s2, o);
    out[(size_t)node * 32 + lane] = v - m - __logf(s2);
}

// ---------------------------------------------------------------------------
// Launch: 6 kernels, no runtime API calls.
// ---------------------------------------------------------------------------
extern "C" void kernel_launch(void* const* d_in, const int* in_sizes, int n_in,
                              void* d_out, int out_size) {
    const float* x   = (const float*)d_in[0];
    const int*   ei  = (const int*)d_in[1];     // int64 coerced to int32 by harness
    const float* W1  = (const float*)d_in[2];
    const float* aS1 = (const float*)d_in[3];
    const float* aD1 = (const float*)d_in[4];
    const float* b1  = (const float*)d_in[5];
    const float* W2  = (const float*)d_in[6];
    const float* aS2 = (const float*)d_in[7];
    const float* aD2 = (const float*)d_in[8];
    const float* b2  = (const float*)d_in[9];
    float* out = (float*)d_out;

    const int n = in_sizes[0] / 128;
    const int e = in_sizes[1] / 2;
    const int etot = e + n;
    const int nb = (n + SCAN_CHUNK - 1) / SCAN_CHUNK;
    const int gemm1_blocks = (n + 63) / 64;

    // [GEMM1+alpha1 | edge histogram]  (g_deg arrives zeroed: invariant)
    fused_gemm1_hist_kernel<<<gemm1_blocks + HIST_BLOCKS, 256>>>(
        x, W1, aS1, aD1, ei, n, e, gemm1_blocks);

    // CSR offsets (single pass) + scatter
    scan_onepass_kernel<<<nb, 256>>>(n, nb);
    scatter_kernel<<<(etot + 255) / 256, 256>>>(ei, e, n, nb);

    // Layer 1 aggregate (+bias+ReLU)
    gather64_kernel<<<(n * 32 + 255) / 256, 256>>>(b1, n);

    // Layer 2
    gemm2_kernel<<<(n + 63) / 64, 256>>>(W2, aS2, aD2, n);
    gather32_kernel<<<(n * 32 + 255) / 256, 256>>>(b2, out, n);
}

// round 8
// speedup vs baseline: 1.3367x; 1.2172x over previous
#include <cuda_runtime.h>
#include <cuda_fp16.h>
#include <cstdint>

#define NMAX 100000
#define EMAX 1600000
#define ETOT (EMAX + NMAX)
#define SCAN_CHUNK 1024
#define NBMAX ((NMAX + SCAN_CHUNK - 1) / SCAN_CHUNK)
#define HIST_BLOCKS 1184

// ---------------------------------------------------------------------------
// Static scratch (zero-initialized at module load; kernels restore the
// zero-invariants they rely on so CUDA-graph replays stay deterministic).
// ---------------------------------------------------------------------------
__device__ __half g_h1h[NMAX * 64];  // x @ W1   (fp16 storage, fp32 accum)
__device__ float  g_o1[NMAX * 64];   // relu(aggregate layer1) = input to GEMM2
__device__ float  g_h2[NMAX * 32];   // o1 @ W2
__device__ float  g_as1[NMAX], g_ad1[NMAX];
__device__ float  g_as2[NMAX], g_ad2[NMAX];
__device__ int    g_deg[NMAX];       // invariant: zero at kernel_launch entry
__device__ int    g_off[NMAX + 1];
__device__ int    g_cur[NMAX];
__device__ int    g_csr[ETOT];
__device__ unsigned long long g_scan[NBMAX];  // invariant: zero at entry

// ---------------------------------------------------------------------------
// Single-pass exclusive scan of (deg[i]+1), decoupled lookback (as R7).
// ---------------------------------------------------------------------------
__global__ void __launch_bounds__(256) scan_onepass_kernel(int n, int nb) {
    __shared__ int sm[256];
    __shared__ int s_excl;
    const int b = blockIdx.x;
    const int t = threadIdx.x;
    const int i0 = b * SCAN_CHUNK + t * 4;

    int v[4];
    int s = 0;
#pragma unroll
    for (int u = 0; u < 4; ++u) {
        int i = i0 + u;
        if (i < n) {
            v[u] = g_deg[i] + 1;
            g_deg[i] = 0;
        } else v[u] = 0;
        s += v[u];
    }
    sm[t] = s;
    __syncthreads();
    for (int st = 1; st < 256; st <<= 1) {
        int a = (t >= st) ? sm[t - st] : 0;
        __syncthreads();
        sm[t] += a;
        __syncthreads();
    }
    const int incl = sm[t];
    const int total = sm[255];

    if (t == 0) {
        unsigned long long pub = ((b == 0) ? (2ULL << 32) : (1ULL << 32)) |
                                 (unsigned int)total;
        atomicExch(&g_scan[b], pub);
        int excl = 0;
        if (b > 0) {
            int j = b - 1;
            for (;;) {
                unsigned long long st2;
                do {
                    st2 = atomicAdd(&g_scan[j], 0ULL);
                    if (!(st2 >> 32)) __nanosleep(40);
                } while (!(st2 >> 32));
                excl += (int)(unsigned int)st2;
                if ((st2 >> 32) == 2ULL) break;
                --j;
            }
            atomicExch(&g_scan[b], (2ULL << 32) | (unsigned int)(excl + total));
        }
        s_excl = excl;
    }
    __syncthreads();

    int pref = s_excl + (incl - s);
#pragma unroll
    for (int u = 0; u < 4; ++u) {
        int i = i0 + u;
        if (i < n) { g_off[i] = pref; g_cur[i] = pref; }
        pref += v[u];
    }
    if (b == nb - 1 && t == 255) g_off[n] = s_excl + total;
}

__global__ void scatter_kernel(const int* __restrict__ ei, int e, int n, int nb) {
    int t = blockIdx.x * blockDim.x + threadIdx.x;
    if (t < nb) g_scan[t] = 0ULL;
    if (t < e) {
        int src = ei[t];
        int dst = ei[e + t];
        int pos = atomicAdd(&g_cur[dst], 1);
        g_csr[pos] = src;
    } else if (t < e + n) {
        int i = t - e;
        int pos = atomicAdd(&g_cur[i], 1);
        g_csr[pos] = i;
    }
}

// ---------------------------------------------------------------------------
// Tensor-core GEMM (HMMA m16n8k16, fp16 in / fp32 accum) + fused alpha.
// Block: 256 threads = 8 warps, output tile 64 nodes x M cols, full K staged.
// Warp w: rows 16*(w>>1), cols (M==64 ? 32 : 16)*(w&1).
// ---------------------------------------------------------------------------
__device__ __forceinline__ void ldsm_x4(uint32_t a[4], uint32_t addr) {
    asm volatile("ldmatrix.sync.aligned.m8n8.x4.shared.b16 {%0,%1,%2,%3},[%4];"
                 : "=r"(a[0]), "=r"(a[1]), "=r"(a[2]), "=r"(a[3]) : "r"(addr));
}
__device__ __forceinline__ void ldsm_x4_t(uint32_t a[4], uint32_t addr) {
    asm volatile("ldmatrix.sync.aligned.m8n8.x4.trans.shared.b16 {%0,%1,%2,%3},[%4];"
                 : "=r"(a[0]), "=r"(a[1]), "=r"(a[2]), "=r"(a[3]) : "r"(addr));
}
__device__ __forceinline__ void mma16816(float c[4], const uint32_t a[4],
                                         const uint32_t* b) {
    asm volatile(
        "mma.sync.aligned.m16n8k16.row.col.f32.f16.f16.f32 "
        "{%0,%1,%2,%3},{%4,%5,%6,%7},{%8,%9},{%0,%1,%2,%3};"
        : "+f"(c[0]), "+f"(c[1]), "+f"(c[2]), "+f"(c[3])
        : "r"(a[0]), "r"(a[1]), "r"(a[2]), "r"(a[3]), "r"(b[0]), "r"(b[1]));
}

template <int K, int M, typename TH>
__device__ __forceinline__ void gemm_mma_body(
    const float* __restrict__ X, const float* __restrict__ W,
    TH* __restrict__ H,
    const float* __restrict__ a_s, const float* __restrict__ a_d,
    float* __restrict__ as_out, float* __restrict__ ad_out,
    int n, int bid)
{
    constexpr int AP = K + 8;         // A smem stride (halves); 2*AP % 16 == 0
    constexpr int NP = M + 8;         // B smem stride (halves)
    constexpr int NT = M / 16;        // n8-tiles per warp (4 or 2)
    constexpr int KS = K / 16;
    __shared__ __half As[64 * AP];
    __shared__ __half Bs[K * NP];
    __shared__ float  sAs[64], sAd[64];

    const int tid = threadIdx.x;
    const int lane = tid & 31;
    const int wid = tid >> 5;
    const int nb = bid * 64;

    if (tid < 64) { sAs[tid] = 0.f; sAd[tid] = 0.f; }

    // Stage A (x rows, fp32 -> fp16)
#pragma unroll
    for (int it = 0; it < K / 16; ++it) {           // 64*K/4 loads / 256 threads
        int idx = tid + it * 256;
        int r = idx / (K / 4);
        int c4 = idx % (K / 4);
        int node = nb + r;
        float4 v = make_float4(0.f, 0.f, 0.f, 0.f);
        if (node < n)
            v = *reinterpret_cast<const float4*>(X + (size_t)node * K + c4 * 4);
        __half2 h0 = __floats2half2_rn(v.x, v.y);
        __half2 h1 = __floats2half2_rn(v.z, v.w);
        uint2 pk = make_uint2(*(uint32_t*)&h0, *(uint32_t*)&h1);
        *reinterpret_cast<uint2*>(&As[r * AP + c4 * 4]) = pk;
    }
    // Stage B (W, fp32 -> fp16), K x M
#pragma unroll
    for (int it = 0; it < (K * M / 4) / 256; ++it) {
        int idx = tid + it * 256;
        int r = idx / (M / 4);
        int c4 = idx % (M / 4);
        float4 v = *reinterpret_cast<const float4*>(W + (size_t)r * M + c4 * 4);
        __half2 h0 = __floats2half2_rn(v.x, v.y);
        __half2 h1 = __floats2half2_rn(v.z, v.w);
        uint2 pk = make_uint2(*(uint32_t*)&h0, *(uint32_t*)&h1);
        *reinterpret_cast<uint2*>(&Bs[r * NP + c4 * 4]) = pk;
    }
    __syncthreads();

    const int r0 = (wid >> 1) * 16;
    const int n0 = (wid & 1) * (M == 64 ? 32 : 16);

    float c[NT][4];
#pragma unroll
    for (int t2 = 0; t2 < NT; ++t2)
#pragma unroll
        for (int u = 0; u < 4; ++u) c[t2][u] = 0.f;

    // A fragment address: row = r0 + (lane&15), half-col = (lane>>4)*8
    const uint32_t aBase = (uint32_t)__cvta_generic_to_shared(As);
    const uint32_t bBase = (uint32_t)__cvta_generic_to_shared(Bs);

#pragma unroll
    for (int kk = 0; kk < KS; ++kk) {
        int k0 = kk * 16;
        uint32_t a[4];
        ldsm_x4(a, aBase + ((r0 + (lane & 15)) * AP + k0 + ((lane >> 4) << 3)) * 2);
#pragma unroll
        for (int tp = 0; tp < NT / 2; ++tp) {
            int ncol = n0 + tp * 16;
            int row = k0 + ((lane >> 3) & 1) * 8 + (lane & 7);
            int col = ncol + (lane >> 4) * 8;
            uint32_t bb[4];
            ldsm_x4_t(bb, bBase + (row * NP + col) * 2);
            mma16816(c[tp * 2], a, bb);
            mma16816(c[tp * 2 + 1], a, bb + 2);
        }
    }

    // Epilogue: store H (+alpha partials via smem atomics)
    const int group = lane >> 2;
    const int qt = lane & 3;
    const int rlo = r0 + group, rhi = rlo + 8;
    const int nlo = nb + rlo, nhi = nb + rhi;
    float slo = 0.f, dlo = 0.f, shi = 0.f, dhi = 0.f;
#pragma unroll
    for (int t2 = 0; t2 < NT; ++t2) {
        int c0 = n0 + t2 * 8 + qt * 2;
        float as0 = a_s[c0], as1 = a_s[c0 + 1];
        float ad0 = a_d[c0], ad1 = a_d[c0 + 1];
        slo += c[t2][0] * as0 + c[t2][1] * as1;
        dlo += c[t2][0] * ad0 + c[t2][1] * ad1;
        shi += c[t2][2] * as0 + c[t2][3] * as1;
        dhi += c[t2][2] * ad0 + c[t2][3] * ad1;
        if (nlo < n) {
            if constexpr (sizeof(TH) == 2) {
                __half2 h = __floats2half2_rn(c[t2][0], c[t2][1]);
                *reinterpret_cast<__half2*>((__half*)H + (size_t)nlo * M + c0) = h;
            } else {
                *reinterpret_cast<float2*>((float*)H + (size_t)nlo * M + c0) =
                    make_float2(c[t2][0], c[t2][1]);
            }
        }
        if (nhi < n) {
            if constexpr (sizeof(TH) == 2) {
                __half2 h = __floats2half2_rn(c[t2][2], c[t2][3]);
                *reinterpret_cast<__half2*>((__half*)H + (size_t)nhi * M + c0) = h;
            } else {
                *reinterpret_cast<float2*>((float*)H + (size_t)nhi * M + c0) =
                    make_float2(c[t2][2], c[t2][3]);
            }
        }
    }
    // reduce over the 4 lanes of each row-group
#pragma unroll
    for (int o = 1; o <= 2; o <<= 1) {
        slo += __shfl_xor_sync(0xffffffffu, slo, o);
        dlo += __shfl_xor_sync(0xffffffffu, dlo, o);
        shi += __shfl_xor_sync(0xffffffffu, shi, o);
        dhi += __shfl_xor_sync(0xffffffffu, dhi, o);
    }
    if (qt == 0) {
        atomicAdd(&sAs[rlo], slo);
        atomicAdd(&sAd[rlo], dlo);
        atomicAdd(&sAs[rhi], shi);
        atomicAdd(&sAd[rhi], dhi);
    }
    __syncthreads();
    if (tid < 64) {
        int node = nb + tid;
        if (node < n) { as_out[node] = sAs[tid]; ad_out[node] = sAd[tid]; }
    }
}

// Fused: GEMM1 (+alpha1) blocks, then histogram blocks.
__global__ void __launch_bounds__(256) fused_gemm1_hist_kernel(
    const float* __restrict__ X, const float* __restrict__ W1,
    const float* __restrict__ aS1, const float* __restrict__ aD1,
    const int* __restrict__ ei, int n, int e, int gemm_blocks)
{
    if ((int)blockIdx.x < gemm_blocks) {
        gemm_mma_body<128, 64, __half>(X, W1, g_h1h, aS1, aD1,
                                       g_as1, g_ad1, n, blockIdx.x);
    } else {
        int hb = gridDim.x - gemm_blocks;
        for (int t = (blockIdx.x - gemm_blocks) * 256 + threadIdx.x; t < e;
             t += hb * 256) {
            int dst = ei[e + t];
            atomicAdd(&g_deg[dst], 1);
        }
    }
}

__global__ void __launch_bounds__(256) gemm2_kernel(
    const float* __restrict__ W2,
    const float* __restrict__ aS2, const float* __restrict__ aD2, int n)
{
    gemm_mma_body<64, 32, float>(g_o1, W2, g_h2, aS2, aD2,
                                 g_as2, g_ad2, n, blockIdx.x);
}

// ---------------------------------------------------------------------------
// Gather layer 1 (unchanged from R7 pass): warp/node, smem-staged weights.
// ---------------------------------------------------------------------------
__global__ void __launch_bounds__(256) gather64_kernel(
    const float* __restrict__ b, int n)
{
    __shared__ float2 stage[8][32];
    int node = (blockIdx.x * blockDim.x + threadIdx.x) >> 5;
    int lane = threadIdx.x & 31;
    int wid = (threadIdx.x >> 5) & 7;
    if (node >= n) return;
    int p0 = g_off[node], p1 = g_off[node + 1];
    float advl = g_ad1[node];
    const __half2* hb = reinterpret_cast<const __half2*>(g_h1h) + lane;
    float sum = 0.f, a0 = 0.f, a1 = 0.f;

    for (int base = p0; base < p1; base += 32) {
        int p = base + lane;
        int src = 0;
        float w = 0.f;
        if (p < p1) {
            src = g_csr[p];
            float ev = g_as1[src] + advl;
            ev = ev > 0.f ? ev : 0.2f * ev;
            w = __expf(ev);
        }
        sum += w;
        stage[wid][lane] = make_float2(w, __int_as_float(src * 32));
        __syncwarp();
        int nc = min(32, p1 - base);
#pragma unroll 4
        for (int j = 0; j < nc; ++j) {
            float2 sj = stage[wid][j];
            float2 hv = __half22float2(hb[__float_as_int(sj.y)]);
            a0 = fmaf(sj.x, hv.x, a0);
            a1 = fmaf(sj.x, hv.y, a1);
        }
        __syncwarp();
    }
#pragma unroll
    for (int o = 16; o; o >>= 1) sum += __shfl_xor_sync(0xffffffffu, sum, o);
    float inv = 1.f / (sum + 1e-16f);
    float2 o;
    o.x = fmaxf(fmaf(a0, inv, b[lane * 2]), 0.f);
    o.y = fmaxf(fmaf(a1, inv, b[lane * 2 + 1]), 0.f);
    *reinterpret_cast<float2*>(g_o1 + (size_t)node * 64 + lane * 2) = o;
}

__global__ void __launch_bounds__(256) gather32_kernel(
    const float* __restrict__ b, float* __restrict__ out, int n)
{
    __shared__ float2 stage[8][32];
    int node = (blockIdx.x * blockDim.x + threadIdx.x) >> 5;
    int lane = threadIdx.x & 31;
    int wid = (threadIdx.x >> 5) & 7;
    if (node >= n) return;
    int p0 = g_off[node], p1 = g_off[node + 1];
    float advl = g_ad2[node];
    const float* hb = g_h2 + lane;
    float sum = 0.f, acc = 0.f;

    for (int base = p0; base < p1; base += 32) {
        int p = base + lane;
        int src = 0;
        float w = 0.f;
        if (p < p1) {
            src = g_csr[p];
            float ev = g_as2[src] + advl;
            ev = ev > 0.f ? ev : 0.2f * ev;
            w = __expf(ev);
        }
        sum += w;
        stage[wid][lane] = make_float2(w, __int_as_float(src * 32));
        __syncwarp();
        int nc = min(32, p1 - base);
#pragma unroll 4
        for (int j = 0; j < nc; ++j) {
            float2 sj = stage[wid][j];
            acc = fmaf(sj.x, hb[__float_as_int(sj.y)], acc);
        }
        __syncwarp();
    }
#pragma unroll
    for (int o = 16; o; o >>= 1) sum += __shfl_xor_sync(0xffffffffu, sum, o);

    float v = fmaf(acc, 1.f / (sum + 1e-16f), b[lane]);
    float m = v;
#pragma unroll
    for (int o = 16; o; o >>= 1) m = fmaxf(m, __shfl_xor_sync(0xffffffffu, m, o));
    float ex = __expf(v - m);
    float s2 = ex;
#pragma unroll
    for (int o = 16; o; o >>= 1) s2 += __shfl_xor_sync(0xffffffffu, s2, o);
    out[(size_t)node * 32 + lane] = v - m - __logf(s2);
}

// ---------------------------------------------------------------------------
// Launch: 6 kernels, no runtime API calls.
// ---------------------------------------------------------------------------
extern "C" void kernel_launch(void* const* d_in, const int* in_sizes, int n_in,
                              void* d_out, int out_size) {
    const float* x   = (const float*)d_in[0];
    const int*   ei  = (const int*)d_in[1];     // int64 coerced to int32 by harness
    const float* W1  = (const float*)d_in[2];
    const float* aS1 = (const float*)d_in[3];
    const float* aD1 = (const float*)d_in[4];
    const float* b1  = (const float*)d_in[5];
    const float* W2  = (const float*)d_in[6];
    const float* aS2 = (const float*)d_in[7];
    const float* aD2 = (const float*)d_in[8];
    const float* b2  = (const float*)d_in[9];
    float* out = (float*)d_out;

    const int n = in_sizes[0] / 128;
    const int e = in_sizes[1] / 2;
    const int etot = e + n;
    const int nb = (n + SCAN_CHUNK - 1) / SCAN_CHUNK;
    const int gemm1_blocks = (n + 63) / 64;

    fused_gemm1_hist_kernel<<<gemm1_blocks + HIST_BLOCKS, 256>>>(
        x, W1, aS1, aD1, ei, n, e, gemm1_blocks);

    scan_onepass_kernel<<<nb, 256>>>(n, nb);
    scatter_kernel<<<(etot + 255) / 256, 256>>>(ei, e, n, nb);

    gather64_kernel<<<(n * 32 + 255) / 256, 256>>>(b1, n);

    gemm2_kernel<<<(n + 63) / 64, 256>>>(W2, aS2, aD2, n);
    gather32_kernel<<<(n * 32 + 255) / 256, 256>>>(b2, out, n);
}